// round 15
// baseline (speedup 1.0000x reference)
#include <cuda_runtime.h>
#include <cuda_fp16.h>
#include <cstdint>

// Problem dims
#define B_  32
#define S_  2048
#define E_  256
#define H_  256
#define M_  (B_ * S_)   // 65536
#define N_  (3 * H_)    // 768
#define K_  (2 * E_)    // 512

#define CHUNKS 64
#define CHLEN  (S_ / CHUNKS)   // 32
#define CHAINS (B_ * H_)       // 8192

// Scratch (static device arrays; no allocation)
__device__ __half g_gates[(size_t)M_ * N_];   // activated z|f|o  [M,768] fp16
__device__ __half g_x16[(size_t)M_ * E_];     // x in fp16
__device__ __half g_Wt16[(size_t)N_ * K_];    // W transposed fp16 [768,512]
__device__ float  g_Ac[(size_t)CHAINS * CHUNKS];  // [chain][q]  chain-major
__device__ float  g_Bc[(size_t)CHAINS * CHUNKS];  // [chain][q]
__device__ float  g_c0[(size_t)CHUNKS * CHAINS];  // [q][chain]  (coalesced p2 store / p3 load)

__device__ __forceinline__ float sigm(float x)      { return 1.0f / (1.0f + __expf(-x)); }
__device__ __forceinline__ float tanh_fast(float x) { return 2.0f / (1.0f + __expf(-2.0f * x)) - 1.0f; }

__device__ __forceinline__ uint32_t smem_u32(const void* p) {
    uint32_t a;
    asm("{ .reg .u64 t; cvta.to.shared.u64 t, %1; cvt.u32.u64 %0, t; }" : "=r"(a) : "l"(p));
    return a;
}

#define LDSM_X4(r0, r1, r2, r3, a)                                              \
    asm volatile("ldmatrix.sync.aligned.m8n8.x4.shared.b16 {%0,%1,%2,%3}, [%4];"\
                 : "=r"(r0), "=r"(r1), "=r"(r2), "=r"(r3) : "r"(a))

#define MMA_F16(c, a0, a1, a2, a3, b0, b1)                                      \
    asm volatile("mma.sync.aligned.m16n8k16.row.col.f32.f16.f16.f32 "           \
                 "{%0,%1,%2,%3}, {%4,%5,%6,%7}, {%8,%9}, {%0,%1,%2,%3};"        \
                 : "+f"((c)[0]), "+f"((c)[1]), "+f"((c)[2]), "+f"((c)[3])       \
                 : "r"(a0), "r"(a1), "r"(a2), "r"(a3), "r"(b0), "r"(b1))

__device__ __forceinline__ void cp16(uint32_t dst, const void* src, int sz) {
    asm volatile("cp.async.cg.shared.global [%0], [%1], 16, %2;" :: "r"(dst), "l"(src), "r"(sz));
}
#define CP_COMMIT() asm volatile("cp.async.commit_group;" ::: "memory")
#define CP_WAIT1()  asm volatile("cp.async.wait_group 1;" ::: "memory")

// ---------------------------------------------------------------------------
// Fused prep: blocks [0, 8192) convert x fp32->fp16 (32B/thread);
// blocks [8192, 8576) transpose+convert W -> Wt16 [768,512].
// ---------------------------------------------------------------------------
#define XBLK (M_ * E_ / 8 / 256)   // 8192
#define WBLK (24 * 16)             // 384

__global__ __launch_bounds__(256)
void prep_fused(const float* __restrict__ x, const float* __restrict__ W)
{
    if (blockIdx.x < XBLK) {
        long i = (long)blockIdx.x * 256 + threadIdx.x;   // one float4 pair each
        const float4* src = (const float4*)x;
        float4 v0 = src[2 * i], v1 = src[2 * i + 1];
        __half2 h0 = __floats2half2_rn(v0.x, v0.y);
        __half2 h1 = __floats2half2_rn(v0.z, v0.w);
        __half2 h2 = __floats2half2_rn(v1.x, v1.y);
        __half2 h3 = __floats2half2_rn(v1.z, v1.w);
        uint4 o;
        o.x = *(uint32_t*)&h0; o.y = *(uint32_t*)&h1;
        o.z = *(uint32_t*)&h2; o.w = *(uint32_t*)&h3;
        *((uint4*)g_x16 + i) = o;
    } else {
        __shared__ float t[32][33];
        int wb = blockIdx.x - XBLK;          // 0..383 = (24 n-blocks) x (16 k-blocks)
        int bxn = wb % 24, byk = wb / 24;
        int tx = threadIdx.x & 31, ty = threadIdx.x >> 5;   // 32 x 8
        int n = bxn * 32 + tx;
        int k = byk * 32 + ty;
#pragma unroll
        for (int j = 0; j < 32; j += 8)
            t[ty + j][tx] = W[(long)(k + j) * N_ + n];
        __syncthreads();
        int n2 = bxn * 32 + ty;
        int k2 = byk * 32 + tx;
#pragma unroll
        for (int j = 0; j < 32; j += 8)
            g_Wt16[(long)(n2 + j) * K_ + k2] = __float2half_rn(t[tx][ty + j]);
    }
}

// ---------------------------------------------------------------------------
// GEMM (best measured, unchanged): gates = [x_t, x_{t-1}] @ W + b.
// fp16 mma.sync m16n8k16, fp32 accum. CTA tile 128x128, BK=64 (8 phases),
// 8 warps (2x4), warp tile 64x32, 3-stage ring / prefetch distance 2,
// single barrier per phase, 256 thr, 2 CTAs/SM (16 warps/SM).
// ---------------------------------------------------------------------------
#define RS        72                      // halves per smem row
#define A_BYTES   (128 * RS * 2)          // 18432
#define STAGE_SZ  (2 * A_BYTES)           // A + B = 36864
#define STAGES    3
#define SMEM_BYTES (STAGES * STAGE_SZ)    // 110592 (2 CTAs = 216 KB <= 228 KB)

__global__ __launch_bounds__(256, 2)
void gates_gemm(const float* __restrict__ bias)
{
    extern __shared__ char smem[];
    const uint32_t sb = smem_u32(smem);
    const int tid  = threadIdx.x;
    const int lane = tid & 31;
    const int wid  = tid >> 5;
    const int warp_m = wid & 1;
    const int warp_n = wid >> 1;
    const int m0 = blockIdx.y * 128;
    const int n0 = blockIdx.x * 128;

    auto stageA = [&](int s) -> uint32_t { return sb + s * STAGE_SZ; };
    auto stageB = [&](int s) -> uint32_t { return sb + s * STAGE_SZ + A_BYTES; };

    float acc[4][4][4];
#pragma unroll
    for (int a = 0; a < 4; a++)
#pragma unroll
        for (int b = 0; b < 4; b++)
#pragma unroll
            for (int c = 0; c < 4; c++) acc[a][b][c] = 0.0f;

    auto load_tile = [&](int kt, int s) {
        const int k0 = kt * 64;
        const uint32_t ab = stageA(s), bb = stageB(s);
#pragma unroll
        for (int i = 0; i < 4; i++) {
            int idx = tid + i * 256;
            int r = idx >> 3, ci = idx & 7;          // row 0..127, 16B chunk 0..7
            uint32_t dst = ab + r * (RS * 2) + ci * 16;
            int m = m0 + r;
            const __half* src;
            int sz = 16;
            if (k0 < 256) {
                src = g_x16 + (long)m * E_ + k0 + ci * 8;
            } else if ((m & (S_ - 1)) == 0) {
                src = g_x16; sz = 0;                  // t==0: zero fill
            } else {
                src = g_x16 + (long)(m - 1) * E_ + (k0 - 256) + ci * 8;
            }
            cp16(dst, src, sz);
        }
#pragma unroll
        for (int i = 0; i < 4; i++) {
            int idx = tid + i * 256;
            int r = idx >> 3, ci = idx & 7;
            uint32_t dst = bb + r * (RS * 2) + ci * 16;
            cp16(dst, g_Wt16 + (long)(n0 + r) * K_ + k0 + ci * 8, 16);
        }
    };

    load_tile(0, 0); CP_COMMIT();
    load_tile(1, 1); CP_COMMIT();

    for (int kt = 0; kt < 8; kt++) {
        const int s = kt % STAGES;
        CP_WAIT1();          // stage s's copies complete (this thread)
        __syncthreads();     // all threads: stage s visible; compute(kt-1) done

        if (kt + 2 < 8) load_tile(kt + 2, (kt + 2) % STAGES);
        CP_COMMIT();         // possibly-empty group keeps wait_group math

        const uint32_t ab = stageA(s), bb = stageB(s);
#pragma unroll
        for (int ks = 0; ks < 4; ks++) {
            const int kk = ks * 16;
            uint32_t af[4][4], bf[4][2];
#pragma unroll
            for (int mt = 0; mt < 4; mt++) {
                int mBase = warp_m * 64 + mt * 16;
                int mi = lane >> 3;
                int row = mBase + ((mi & 1) << 3) + (lane & 7);
                int col = kk + ((mi >> 1) << 3);
                uint32_t a = ab + (row * RS + col) * 2;
                LDSM_X4(af[mt][0], af[mt][1], af[mt][2], af[mt][3], a);
            }
#pragma unroll
            for (int p = 0; p < 2; p++) {
                int nBase = warp_n * 32 + p * 16;
                int mi = lane >> 3;
                int row = nBase + ((mi >> 1) << 3) + (lane & 7);
                int col = kk + ((mi & 1) << 3);
                uint32_t a = bb + (row * RS + col) * 2;
                LDSM_X4(bf[2 * p][0], bf[2 * p][1], bf[2 * p + 1][0], bf[2 * p + 1][1], a);
            }
#pragma unroll
            for (int mt = 0; mt < 4; mt++)
#pragma unroll
                for (int nt = 0; nt < 4; nt++)
                    MMA_F16(acc[mt][nt], af[mt][0], af[mt][1], af[mt][2], af[mt][3],
                            bf[nt][0], bf[nt][1]);
        }
    }

    // Epilogue: bias + activation, write g_gates fp16
#pragma unroll
    for (int mt = 0; mt < 4; mt++) {
#pragma unroll
        for (int nt = 0; nt < 4; nt++) {
            int r   = m0 + warp_m * 64 + mt * 16 + (lane >> 2);
            int cgl = n0 + warp_n * 32 + nt * 8 + ((lane & 3) << 1);
            bool isz = (cgl < 256);
            float b0 = __ldg(bias + cgl);
            float b1 = __ldg(bias + cgl + 1);
            float v0 = acc[mt][nt][0] + b0;
            float v1 = acc[mt][nt][1] + b1;
            float v2 = acc[mt][nt][2] + b0;
            float v3 = acc[mt][nt][3] + b1;
            if (isz) {
                v0 = tanh_fast(v0); v1 = tanh_fast(v1);
                v2 = tanh_fast(v2); v3 = tanh_fast(v3);
            } else {
                v0 = sigm(v0); v1 = sigm(v1);
                v2 = sigm(v2); v3 = sigm(v3);
            }
            *(__half2*)&g_gates[(long)r * N_ + cgl]       = __floats2half2_rn(v0, v1);
            *(__half2*)&g_gates[(long)(r + 8) * N_ + cgl] = __floats2half2_rn(v2, v3);
        }
    }
}

// ---------------------------------------------------------------------------
// Scan pass 1: per (chain-pair, chunk): A = prod(f), B = c(chunk | c_in = 0)
// 2048 x 128 thr; 2 h per thread (half2). CHLEN=32.
// Writes chain-major [chain][q] (strided 4B stores; tiny traffic).
// ---------------------------------------------------------------------------
__global__ __launch_bounds__(128)
void scan_p1()
{
    const int b = blockIdx.x >> 6, q = blockIdx.x & 63, h2 = threadIdx.x;
    const __half2* gp = (const __half2*)(g_gates + (long)(b * S_ + q * CHLEN) * N_) + h2;

    float ax = 1.0f, ay = 1.0f, cx = 0.0f, cy = 0.0f;
    for (int t0 = 0; t0 < CHLEN; t0 += 8) {
        __half2 z2[8], f2[8];
#pragma unroll
        for (int j = 0; j < 8; j++) {
            const __half2* p = gp + (long)(t0 + j) * (N_ / 2);
            z2[j] = __ldg(p);
            f2[j] = __ldg(p + 128);
        }
#pragma unroll
        for (int j = 0; j < 8; j++) {
            float2 z = __half22float2(z2[j]);
            float2 f = __half22float2(f2[j]);
            cx = fmaf(f.x, cx - z.x, z.x);
            cy = fmaf(f.y, cy - z.y, z.y);
            ax *= f.x; ay *= f.y;
        }
    }
    const int chain = b * H_ + 2 * h2;
    g_Ac[(size_t)chain * CHUNKS + q]       = ax;
    g_Ac[(size_t)(chain + 1) * CHUNKS + q] = ay;
    g_Bc[(size_t)chain * CHUNKS + q]       = cx;
    g_Bc[(size_t)(chain + 1) * CHUNKS + q] = cy;
}

// ---------------------------------------------------------------------------
// Scan pass 2: sequential combine over 64 chunks -> chunk-initial c.
// 64 x 128 thr; per-thread A/B are CONTIGUOUS (chain-major) -> 32 float4
// loads, MLP~32, then a pure-FMA 64-step chain. c0 stored [q][chain]
// (coalesced stores here, coalesced loads in p3).
// ---------------------------------------------------------------------------
__global__ __launch_bounds__(128)
void scan_p2()
{
    const int chain = blockIdx.x * 128 + threadIdx.x;
    const float4* Ap = (const float4*)&g_Ac[(size_t)chain * CHUNKS];
    const float4* Bp = (const float4*)&g_Bc[(size_t)chain * CHUNKS];
    float4 Aa[CHUNKS / 4], Bb[CHUNKS / 4];
#pragma unroll
    for (int i = 0; i < CHUNKS / 4; i++) {
        Aa[i] = __ldg(Ap + i);
        Bb[i] = __ldg(Bp + i);
    }
    float c = 0.0f;
#pragma unroll
    for (int i = 0; i < CHUNKS / 4; i++) {
        g_c0[(size_t)(4 * i + 0) * CHAINS + chain] = c;
        c = fmaf(Aa[i].x, c, Bb[i].x);
        g_c0[(size_t)(4 * i + 1) * CHAINS + chain] = c;
        c = fmaf(Aa[i].y, c, Bb[i].y);
        g_c0[(size_t)(4 * i + 2) * CHAINS + chain] = c;
        c = fmaf(Aa[i].z, c, Bb[i].z);
        g_c0[(size_t)(4 * i + 3) * CHAINS + chain] = c;
        c = fmaf(Aa[i].w, c, Bb[i].w);
    }
}

// ---------------------------------------------------------------------------
// Scan pass 3: within-chunk scan with correct initial c; write outputs.
// 2048 x 128 thr; half2 gates, float2 stores. CHLEN=32.
// ---------------------------------------------------------------------------
__global__ __launch_bounds__(128)
void scan_p3(const int* __restrict__ mask, float* __restrict__ out)
{
    const int b = blockIdx.x >> 6, q = blockIdx.x & 63, h2 = threadIdx.x;
    const int chain = b * H_ + 2 * h2;
    const __half2* gp = (const __half2*)(g_gates + (long)(b * S_ + q * CHLEN) * N_) + h2;

    int idx = mask[b] - 1;
    if (idx < 0) idx = 0;
    if (idx > S_ - 1) idx = S_ - 1;

    float* outT    = out + (long)(b * S_ + q * CHLEN) * H_ + 2 * h2;
    float* outHid  = out + (long)B_ * S_ * H_;
    float* outCell = outHid + B_ * H_;

    float2 c = *(const float2*)&g_c0[(size_t)q * CHAINS + chain];
    for (int t0 = 0; t0 < CHLEN; t0 += 8) {
        __half2 z2[8], f2[8], o2[8];
#pragma unroll
        for (int j = 0; j < 8; j++) {
            const __half2* p = gp + (long)(t0 + j) * (N_ / 2);
            z2[j] = __ldg(p);
            f2[j] = __ldg(p + 128);
            o2[j] = __ldg(p + 256);
        }
#pragma unroll
        for (int j = 0; j < 8; j++) {
            float2 z = __half22float2(z2[j]);
            float2 f = __half22float2(f2[j]);
            float2 o = __half22float2(o2[j]);
            c.x = fmaf(f.x, c.x - z.x, z.x);
            c.y = fmaf(f.y, c.y - z.y, z.y);
            float2 hv = make_float2(o.x * c.x, o.y * c.y);
            *(float2*)(outT + (long)(t0 + j) * H_) = hv;
            if (q * CHLEN + t0 + j == idx) {
                *(float2*)&outHid[chain]  = hv;
                *(float2*)&outCell[chain] = c;
            }
        }
    }
}

extern "C" void kernel_launch(void* const* d_in, const int* in_sizes, int n_in,
                              void* d_out, int out_size)
{
    const float* x    = (const float*)d_in[0];
    const int*   mask = (const int*)d_in[1];
    const float* W    = (const float*)d_in[2];
    const float* bias = (const float*)d_in[3];
    float* out = (float*)d_out;

    cudaFuncSetAttribute(gates_gemm, cudaFuncAttributeMaxDynamicSharedMemorySize, SMEM_BYTES);

    prep_fused<<<XBLK + WBLK, 256>>>(x, W);
    gates_gemm<<<dim3(6, 512), 256, SMEM_BYTES>>>(bias);
    scan_p1<<<B_ * CHUNKS, 128>>>();
    scan_p2<<<CHAINS / 128, 128>>>();
    scan_p3<<<B_ * CHUNKS, 128>>>(mask, out);
}

// round 16
// speedup vs baseline: 1.0027x; 1.0027x over previous
#include <cuda_runtime.h>
#include <cuda_fp16.h>
#include <cstdint>

// Problem dims
#define B_  32
#define S_  2048
#define E_  256
#define H_  256
#define M_  (B_ * S_)   // 65536
#define N_  (3 * H_)    // 768
#define K_  (2 * E_)    // 512

#define CHUNKS 32
#define CHLEN  (S_ / CHUNKS)   // 64
#define CHAINS (B_ * H_)       // 8192

// Scratch (static device arrays; no allocation)
__device__ __half g_gates[(size_t)M_ * N_];   // activated z|f|o  [M,768] fp16
__device__ __half g_x16[(size_t)M_ * E_];     // x in fp16
__device__ __half g_Wt16[(size_t)N_ * K_];    // W transposed fp16 [768,512]
__device__ float  g_Ac[CHUNKS * CHAINS];      // [q][chain]
__device__ float  g_Bc[CHUNKS * CHAINS];      // [q][chain]
__device__ float  g_c0[CHUNKS * CHAINS];      // [q][chain]

__device__ __forceinline__ float sigm(float x)      { return 1.0f / (1.0f + __expf(-x)); }
__device__ __forceinline__ float tanh_fast(float x) { return 2.0f / (1.0f + __expf(-2.0f * x)) - 1.0f; }

__device__ __forceinline__ uint32_t smem_u32(const void* p) {
    uint32_t a;
    asm("{ .reg .u64 t; cvta.to.shared.u64 t, %1; cvt.u32.u64 %0, t; }" : "=r"(a) : "l"(p));
    return a;
}

#define LDSM_X4(r0, r1, r2, r3, a)                                              \
    asm volatile("ldmatrix.sync.aligned.m8n8.x4.shared.b16 {%0,%1,%2,%3}, [%4];"\
                 : "=r"(r0), "=r"(r1), "=r"(r2), "=r"(r3) : "r"(a))

#define MMA_F16(c, a0, a1, a2, a3, b0, b1)                                      \
    asm volatile("mma.sync.aligned.m16n8k16.row.col.f32.f16.f16.f32 "           \
                 "{%0,%1,%2,%3}, {%4,%5,%6,%7}, {%8,%9}, {%0,%1,%2,%3};"        \
                 : "+f"((c)[0]), "+f"((c)[1]), "+f"((c)[2]), "+f"((c)[3])       \
                 : "r"(a0), "r"(a1), "r"(a2), "r"(a3), "r"(b0), "r"(b1))

__device__ __forceinline__ void cp16(uint32_t dst, const void* src, int sz) {
    asm volatile("cp.async.cg.shared.global [%0], [%1], 16, %2;" :: "r"(dst), "l"(src), "r"(sz));
}
#define CP_COMMIT() asm volatile("cp.async.commit_group;" ::: "memory")
#define CP_WAIT1()  asm volatile("cp.async.wait_group 1;" ::: "memory")

// ---------------------------------------------------------------------------
// Fused prep: blocks [0, 8192) convert x fp32->fp16 (32B/thread);
// blocks [8192, 8576) transpose+convert W -> Wt16 [768,512].
// ---------------------------------------------------------------------------
#define XBLK (M_ * E_ / 8 / 256)   // 8192
#define WBLK (24 * 16)             // 384

__global__ __launch_bounds__(256)
void prep_fused(const float* __restrict__ x, const float* __restrict__ W)
{
    if (blockIdx.x < XBLK) {
        long i = (long)blockIdx.x * 256 + threadIdx.x;   // one float4 pair each
        const float4* src = (const float4*)x;
        float4 v0 = src[2 * i], v1 = src[2 * i + 1];
        __half2 h0 = __floats2half2_rn(v0.x, v0.y);
        __half2 h1 = __floats2half2_rn(v0.z, v0.w);
        __half2 h2 = __floats2half2_rn(v1.x, v1.y);
        __half2 h3 = __floats2half2_rn(v1.z, v1.w);
        uint4 o;
        o.x = *(uint32_t*)&h0; o.y = *(uint32_t*)&h1;
        o.z = *(uint32_t*)&h2; o.w = *(uint32_t*)&h3;
        *((uint4*)g_x16 + i) = o;
    } else {
        __shared__ float t[32][33];
        int wb = blockIdx.x - XBLK;          // 0..383 = (24 n-blocks) x (16 k-blocks)
        int bxn = wb % 24, byk = wb / 24;
        int tx = threadIdx.x & 31, ty = threadIdx.x >> 5;   // 32 x 8
        int n = bxn * 32 + tx;
        int k = byk * 32 + ty;
#pragma unroll
        for (int j = 0; j < 32; j += 8)
            t[ty + j][tx] = W[(long)(k + j) * N_ + n];
        __syncthreads();
        int n2 = bxn * 32 + ty;
        int k2 = byk * 32 + tx;
#pragma unroll
        for (int j = 0; j < 32; j += 8)
            g_Wt16[(long)(n2 + j) * K_ + k2] = __float2half_rn(t[tx][ty + j]);
    }
}

// ---------------------------------------------------------------------------
// GEMM (best measured, unchanged): gates = [x_t, x_{t-1}] @ W + b.
// fp16 mma.sync m16n8k16, fp32 accum. CTA tile 128x128, BK=64 (8 phases),
// 8 warps (2x4), warp tile 64x32, 3-stage ring / prefetch distance 2,
// single barrier per phase, 256 thr, 2 CTAs/SM (16 warps/SM).
// ---------------------------------------------------------------------------
#define RS        72                      // halves per smem row
#define A_BYTES   (128 * RS * 2)          // 18432
#define STAGE_SZ  (2 * A_BYTES)           // A + B = 36864
#define STAGES    3
#define SMEM_BYTES (STAGES * STAGE_SZ)    // 110592 (2 CTAs = 216 KB <= 228 KB)

__global__ __launch_bounds__(256, 2)
void gates_gemm(const float* __restrict__ bias)
{
    extern __shared__ char smem[];
    const uint32_t sb = smem_u32(smem);
    const int tid  = threadIdx.x;
    const int lane = tid & 31;
    const int wid  = tid >> 5;
    const int warp_m = wid & 1;
    const int warp_n = wid >> 1;
    const int m0 = blockIdx.y * 128;
    const int n0 = blockIdx.x * 128;

    auto stageA = [&](int s) -> uint32_t { return sb + s * STAGE_SZ; };
    auto stageB = [&](int s) -> uint32_t { return sb + s * STAGE_SZ + A_BYTES; };

    float acc[4][4][4];
#pragma unroll
    for (int a = 0; a < 4; a++)
#pragma unroll
        for (int b = 0; b < 4; b++)
#pragma unroll
            for (int c = 0; c < 4; c++) acc[a][b][c] = 0.0f;

    auto load_tile = [&](int kt, int s) {
        const int k0 = kt * 64;
        const uint32_t ab = stageA(s), bb = stageB(s);
#pragma unroll
        for (int i = 0; i < 4; i++) {
            int idx = tid + i * 256;
            int r = idx >> 3, ci = idx & 7;          // row 0..127, 16B chunk 0..7
            uint32_t dst = ab + r * (RS * 2) + ci * 16;
            int m = m0 + r;
            const __half* src;
            int sz = 16;
            if (k0 < 256) {
                src = g_x16 + (long)m * E_ + k0 + ci * 8;
            } else if ((m & (S_ - 1)) == 0) {
                src = g_x16; sz = 0;                  // t==0: zero fill
            } else {
                src = g_x16 + (long)(m - 1) * E_ + (k0 - 256) + ci * 8;
            }
            cp16(dst, src, sz);
        }
#pragma unroll
        for (int i = 0; i < 4; i++) {
            int idx = tid + i * 256;
            int r = idx >> 3, ci = idx & 7;
            uint32_t dst = bb + r * (RS * 2) + ci * 16;
            cp16(dst, g_Wt16 + (long)(n0 + r) * K_ + k0 + ci * 8, 16);
        }
    };

    load_tile(0, 0); CP_COMMIT();
    load_tile(1, 1); CP_COMMIT();

    for (int kt = 0; kt < 8; kt++) {
        const int s = kt % STAGES;
        CP_WAIT1();          // stage s's copies complete (this thread)
        __syncthreads();     // all threads: stage s visible; compute(kt-1) done

        if (kt + 2 < 8) load_tile(kt + 2, (kt + 2) % STAGES);
        CP_COMMIT();         // possibly-empty group keeps wait_group math

        const uint32_t ab = stageA(s), bb = stageB(s);
#pragma unroll
        for (int ks = 0; ks < 4; ks++) {
            const int kk = ks * 16;
            uint32_t af[4][4], bf[4][2];
#pragma unroll
            for (int mt = 0; mt < 4; mt++) {
                int mBase = warp_m * 64 + mt * 16;
                int mi = lane >> 3;
                int row = mBase + ((mi & 1) << 3) + (lane & 7);
                int col = kk + ((mi >> 1) << 3);
                uint32_t a = ab + (row * RS + col) * 2;
                LDSM_X4(af[mt][0], af[mt][1], af[mt][2], af[mt][3], a);
            }
#pragma unroll
            for (int p = 0; p < 2; p++) {
                int nBase = warp_n * 32 + p * 16;
                int mi = lane >> 3;
                int row = nBase + ((mi >> 1) << 3) + (lane & 7);
                int col = kk + ((mi & 1) << 3);
                uint32_t a = bb + (row * RS + col) * 2;
                LDSM_X4(bf[2 * p][0], bf[2 * p][1], bf[2 * p + 1][0], bf[2 * p + 1][1], a);
            }
#pragma unroll
            for (int mt = 0; mt < 4; mt++)
#pragma unroll
                for (int nt = 0; nt < 4; nt++)
                    MMA_F16(acc[mt][nt], af[mt][0], af[mt][1], af[mt][2], af[mt][3],
                            bf[nt][0], bf[nt][1]);
        }
    }

    // Epilogue: bias + activation, write g_gates fp16
#pragma unroll
    for (int mt = 0; mt < 4; mt++) {
#pragma unroll
        for (int nt = 0; nt < 4; nt++) {
            int r   = m0 + warp_m * 64 + mt * 16 + (lane >> 2);
            int cgl = n0 + warp_n * 32 + nt * 8 + ((lane & 3) << 1);
            bool isz = (cgl < 256);
            float b0 = __ldg(bias + cgl);
            float b1 = __ldg(bias + cgl + 1);
            float v0 = acc[mt][nt][0] + b0;
            float v1 = acc[mt][nt][1] + b1;
            float v2 = acc[mt][nt][2] + b0;
            float v3 = acc[mt][nt][3] + b1;
            if (isz) {
                v0 = tanh_fast(v0); v1 = tanh_fast(v1);
                v2 = tanh_fast(v2); v3 = tanh_fast(v3);
            } else {
                v0 = sigm(v0); v1 = sigm(v1);
                v2 = sigm(v2); v3 = sigm(v3);
            }
            *(__half2*)&g_gates[(long)r * N_ + cgl]       = __floats2half2_rn(v0, v1);
            *(__half2*)&g_gates[(long)(r + 8) * N_ + cgl] = __floats2half2_rn(v2, v3);
        }
    }
}

// ---------------------------------------------------------------------------
// Scan pass 1 (R14 config): per (chain-pair, chunk): A = prod(f), B = c(chunk)
// 1024 x 128 thr; 2 h per thread (half2). CHLEN=64. Coalesced float2 stores.
// ---------------------------------------------------------------------------
__global__ __launch_bounds__(128)
void scan_p1()
{
    const int b = blockIdx.x >> 5, q = blockIdx.x & 31, h2 = threadIdx.x;
    const __half2* gp = (const __half2*)(g_gates + (long)(b * S_ + q * CHLEN) * N_) + h2;

    float ax = 1.0f, ay = 1.0f, cx = 0.0f, cy = 0.0f;
    for (int t0 = 0; t0 < CHLEN; t0 += 8) {
        __half2 z2[8], f2[8];
#pragma unroll
        for (int j = 0; j < 8; j++) {
            const __half2* p = gp + (long)(t0 + j) * (N_ / 2);
            z2[j] = __ldg(p);
            f2[j] = __ldg(p + 128);
        }
#pragma unroll
        for (int j = 0; j < 8; j++) {
            float2 z = __half22float2(z2[j]);
            float2 f = __half22float2(f2[j]);
            cx = fmaf(f.x, cx - z.x, z.x);
            cy = fmaf(f.y, cy - z.y, z.y);
            ax *= f.x; ay *= f.y;
        }
    }
    const int chain = b * H_ + 2 * h2;
    *(float2*)&g_Ac[q * CHAINS + chain] = make_float2(ax, ay);
    *(float2*)&g_Bc[q * CHAINS + chain] = make_float2(cx, cy);
}

// ---------------------------------------------------------------------------
// Scan pass 2: sequential combine over 32 chunks -> chunk-initial c.
// One thread owns 4 ADJACENT chains: in [q][chain] layout every A/B load and
// c0 store is a contiguous float4, and the thread runs 4 independent FMA
// chains (ILP=4). 16 blocks x 128 thr; fully unrolled so subsequent loads
// slide under current FMAs.
// ---------------------------------------------------------------------------
__global__ __launch_bounds__(128)
void scan_p2()
{
    const int c4 = (blockIdx.x * 128 + threadIdx.x) * 4;   // first of 4 chains
    float4 c = make_float4(0.f, 0.f, 0.f, 0.f);
#pragma unroll
    for (int q = 0; q < CHUNKS; q++) {
        float4 A = __ldg((const float4*)&g_Ac[q * CHAINS + c4]);
        float4 Bv = __ldg((const float4*)&g_Bc[q * CHAINS + c4]);
        *(float4*)&g_c0[q * CHAINS + c4] = c;
        c.x = fmaf(A.x, c.x, Bv.x);
        c.y = fmaf(A.y, c.y, Bv.y);
        c.z = fmaf(A.z, c.z, Bv.z);
        c.w = fmaf(A.w, c.w, Bv.w);
    }
}

// ---------------------------------------------------------------------------
// Scan pass 3 (R14 config): within-chunk scan with correct initial c.
// 1024 x 128 thr; half2 gates, float2 stores. CHLEN=64.
// ---------------------------------------------------------------------------
__global__ __launch_bounds__(128)
void scan_p3(const int* __restrict__ mask, float* __restrict__ out)
{
    const int b = blockIdx.x >> 5, q = blockIdx.x & 31, h2 = threadIdx.x;
    const int chain = b * H_ + 2 * h2;
    const __half2* gp = (const __half2*)(g_gates + (long)(b * S_ + q * CHLEN) * N_) + h2;

    int idx = mask[b] - 1;
    if (idx < 0) idx = 0;
    if (idx > S_ - 1) idx = S_ - 1;

    float* outT    = out + (long)(b * S_ + q * CHLEN) * H_ + 2 * h2;
    float* outHid  = out + (long)B_ * S_ * H_;
    float* outCell = outHid + B_ * H_;

    float2 c = *(const float2*)&g_c0[q * CHAINS + chain];
    for (int t0 = 0; t0 < CHLEN; t0 += 8) {
        __half2 z2[8], f2[8], o2[8];
#pragma unroll
        for (int j = 0; j < 8; j++) {
            const __half2* p = gp + (long)(t0 + j) * (N_ / 2);
            z2[j] = __ldg(p);
            f2[j] = __ldg(p + 128);
            o2[j] = __ldg(p + 256);
        }
#pragma unroll
        for (int j = 0; j < 8; j++) {
            float2 z = __half22float2(z2[j]);
            float2 f = __half22float2(f2[j]);
            float2 o = __half22float2(o2[j]);
            c.x = fmaf(f.x, c.x - z.x, z.x);
            c.y = fmaf(f.y, c.y - z.y, z.y);
            float2 hv = make_float2(o.x * c.x, o.y * c.y);
            *(float2*)(outT + (long)(t0 + j) * H_) = hv;
            if (q * CHLEN + t0 + j == idx) {
                *(float2*)&outHid[chain]  = hv;
                *(float2*)&outCell[chain] = c;
            }
        }
    }
}

extern "C" void kernel_launch(void* const* d_in, const int* in_sizes, int n_in,
                              void* d_out, int out_size)
{
    const float* x    = (const float*)d_in[0];
    const int*   mask = (const int*)d_in[1];
    const float* W    = (const float*)d_in[2];
    const float* bias = (const float*)d_in[3];
    float* out = (float*)d_out;

    cudaFuncSetAttribute(gates_gemm, cudaFuncAttributeMaxDynamicSharedMemorySize, SMEM_BYTES);

    prep_fused<<<XBLK + WBLK, 256>>>(x, W);
    gates_gemm<<<dim3(6, 512), 256, SMEM_BYTES>>>(bias);
    scan_p1<<<B_ * CHUNKS, 128>>>();
    scan_p2<<<CHAINS / 4 / 128, 128>>>();
    scan_p3<<<B_ * CHUNKS, 128>>>(mask, out);
}

// round 17
// speedup vs baseline: 1.0123x; 1.0096x over previous
#include <cuda_runtime.h>
#include <cuda_fp16.h>
#include <cstdint>

// Problem dims
#define B_  32
#define S_  2048
#define E_  256
#define H_  256
#define M_  (B_ * S_)   // 65536
#define N_  (3 * H_)    // 768
#define K_  (2 * E_)    // 512

#define CHUNKS 32
#define CHLEN  (S_ / CHUNKS)   // 64
#define CHAINS (B_ * H_)       // 8192

// Scratch (static device arrays; no allocation)
__device__ __half g_gates[(size_t)M_ * N_];   // activated z|f|o  [M,768] fp16
__device__ __half g_x16[(size_t)M_ * E_];     // x in fp16
__device__ __half g_Wt16[(size_t)N_ * K_];    // W transposed fp16 [768,512]
__device__ float  g_Ac[CHUNKS * CHAINS];      // [q][chain]
__device__ float  g_Bc[CHUNKS * CHAINS];      // [q][chain]
__device__ float  g_c0[CHUNKS * CHAINS];      // [q][chain]

__device__ __forceinline__ float sigm(float x)      { return 1.0f / (1.0f + __expf(-x)); }
__device__ __forceinline__ float tanh_fast(float x) { return 2.0f / (1.0f + __expf(-2.0f * x)) - 1.0f; }

__device__ __forceinline__ uint32_t smem_u32(const void* p) {
    uint32_t a;
    asm("{ .reg .u64 t; cvta.to.shared.u64 t, %1; cvt.u32.u64 %0, t; }" : "=r"(a) : "l"(p));
    return a;
}

#define LDSM_X4(r0, r1, r2, r3, a)                                              \
    asm volatile("ldmatrix.sync.aligned.m8n8.x4.shared.b16 {%0,%1,%2,%3}, [%4];"\
                 : "=r"(r0), "=r"(r1), "=r"(r2), "=r"(r3) : "r"(a))

#define MMA_F16(c, a0, a1, a2, a3, b0, b1)                                      \
    asm volatile("mma.sync.aligned.m16n8k16.row.col.f32.f16.f16.f32 "           \
                 "{%0,%1,%2,%3}, {%4,%5,%6,%7}, {%8,%9}, {%0,%1,%2,%3};"        \
                 : "+f"((c)[0]), "+f"((c)[1]), "+f"((c)[2]), "+f"((c)[3])       \
                 : "r"(a0), "r"(a1), "r"(a2), "r"(a3), "r"(b0), "r"(b1))

__device__ __forceinline__ void cp16(uint32_t dst, const void* src, int sz) {
    asm volatile("cp.async.cg.shared.global [%0], [%1], 16, %2;" :: "r"(dst), "l"(src), "r"(sz));
}
#define CP_COMMIT() asm volatile("cp.async.commit_group;" ::: "memory")
#define CP_WAIT1()  asm volatile("cp.async.wait_group 1;" ::: "memory")

// ---------------------------------------------------------------------------
// Fused prep: blocks [0, 8192) convert x fp32->fp16 (32B/thread);
// blocks [8192, 8576) transpose+convert W -> Wt16 [768,512].
// ---------------------------------------------------------------------------
#define XBLK (M_ * E_ / 8 / 256)   // 8192
#define WBLK (24 * 16)             // 384

__global__ __launch_bounds__(256)
void prep_fused(const float* __restrict__ x, const float* __restrict__ W)
{
    if (blockIdx.x < XBLK) {
        long i = (long)blockIdx.x * 256 + threadIdx.x;   // one float4 pair each
        const float4* src = (const float4*)x;
        float4 v0 = src[2 * i], v1 = src[2 * i + 1];
        __half2 h0 = __floats2half2_rn(v0.x, v0.y);
        __half2 h1 = __floats2half2_rn(v0.z, v0.w);
        __half2 h2 = __floats2half2_rn(v1.x, v1.y);
        __half2 h3 = __floats2half2_rn(v1.z, v1.w);
        uint4 o;
        o.x = *(uint32_t*)&h0; o.y = *(uint32_t*)&h1;
        o.z = *(uint32_t*)&h2; o.w = *(uint32_t*)&h3;
        *((uint4*)g_x16 + i) = o;
    } else {
        __shared__ float t[32][33];
        int wb = blockIdx.x - XBLK;          // 0..383 = (24 n-blocks) x (16 k-blocks)
        int bxn = wb % 24, byk = wb / 24;
        int tx = threadIdx.x & 31, ty = threadIdx.x >> 5;   // 32 x 8
        int n = bxn * 32 + tx;
        int k = byk * 32 + ty;
#pragma unroll
        for (int j = 0; j < 32; j += 8)
            t[ty + j][tx] = W[(long)(k + j) * N_ + n];
        __syncthreads();
        int n2 = bxn * 32 + ty;
        int k2 = byk * 32 + tx;
#pragma unroll
        for (int j = 0; j < 32; j += 8)
            g_Wt16[(long)(n2 + j) * K_ + k2] = __float2half_rn(t[tx][ty + j]);
    }
}

// ---------------------------------------------------------------------------
// GEMM (best measured, unchanged): gates = [x_t, x_{t-1}] @ W + b.
// fp16 mma.sync m16n8k16, fp32 accum. CTA tile 128x128, BK=64 (8 phases),
// 8 warps (2x4), warp tile 64x32, 3-stage ring / prefetch distance 2,
// single barrier per phase, 256 thr, 2 CTAs/SM (16 warps/SM).
// ---------------------------------------------------------------------------
#define RS        72                      // halves per smem row
#define A_BYTES   (128 * RS * 2)          // 18432
#define STAGE_SZ  (2 * A_BYTES)           // A + B = 36864
#define STAGES    3
#define SMEM_BYTES (STAGES * STAGE_SZ)    // 110592 (2 CTAs = 216 KB <= 228 KB)

__global__ __launch_bounds__(256, 2)
void gates_gemm(const float* __restrict__ bias)
{
    extern __shared__ char smem[];
    const uint32_t sb = smem_u32(smem);
    const int tid  = threadIdx.x;
    const int lane = tid & 31;
    const int wid  = tid >> 5;
    const int warp_m = wid & 1;
    const int warp_n = wid >> 1;
    const int m0 = blockIdx.y * 128;
    const int n0 = blockIdx.x * 128;

    auto stageA = [&](int s) -> uint32_t { return sb + s * STAGE_SZ; };
    auto stageB = [&](int s) -> uint32_t { return sb + s * STAGE_SZ + A_BYTES; };

    float acc[4][4][4];
#pragma unroll
    for (int a = 0; a < 4; a++)
#pragma unroll
        for (int b = 0; b < 4; b++)
#pragma unroll
            for (int c = 0; c < 4; c++) acc[a][b][c] = 0.0f;

    auto load_tile = [&](int kt, int s) {
        const int k0 = kt * 64;
        const uint32_t ab = stageA(s), bb = stageB(s);
#pragma unroll
        for (int i = 0; i < 4; i++) {
            int idx = tid + i * 256;
            int r = idx >> 3, ci = idx & 7;          // row 0..127, 16B chunk 0..7
            uint32_t dst = ab + r * (RS * 2) + ci * 16;
            int m = m0 + r;
            const __half* src;
            int sz = 16;
            if (k0 < 256) {
                src = g_x16 + (long)m * E_ + k0 + ci * 8;
            } else if ((m & (S_ - 1)) == 0) {
                src = g_x16; sz = 0;                  // t==0: zero fill
            } else {
                src = g_x16 + (long)(m - 1) * E_ + (k0 - 256) + ci * 8;
            }
            cp16(dst, src, sz);
        }
#pragma unroll
        for (int i = 0; i < 4; i++) {
            int idx = tid + i * 256;
            int r = idx >> 3, ci = idx & 7;
            uint32_t dst = bb + r * (RS * 2) + ci * 16;
            cp16(dst, g_Wt16 + (long)(n0 + r) * K_ + k0 + ci * 8, 16);
        }
    };

    load_tile(0, 0); CP_COMMIT();
    load_tile(1, 1); CP_COMMIT();

    for (int kt = 0; kt < 8; kt++) {
        const int s = kt % STAGES;
        CP_WAIT1();          // stage s's copies complete (this thread)
        __syncthreads();     // all threads: stage s visible; compute(kt-1) done

        if (kt + 2 < 8) load_tile(kt + 2, (kt + 2) % STAGES);
        CP_COMMIT();         // possibly-empty group keeps wait_group math

        const uint32_t ab = stageA(s), bb = stageB(s);
#pragma unroll
        for (int ks = 0; ks < 4; ks++) {
            const int kk = ks * 16;
            uint32_t af[4][4], bf[4][2];
#pragma unroll
            for (int mt = 0; mt < 4; mt++) {
                int mBase = warp_m * 64 + mt * 16;
                int mi = lane >> 3;
                int row = mBase + ((mi & 1) << 3) + (lane & 7);
                int col = kk + ((mi >> 1) << 3);
                uint32_t a = ab + (row * RS + col) * 2;
                LDSM_X4(af[mt][0], af[mt][1], af[mt][2], af[mt][3], a);
            }
#pragma unroll
            for (int p = 0; p < 2; p++) {
                int nBase = warp_n * 32 + p * 16;
                int mi = lane >> 3;
                int row = nBase + ((mi >> 1) << 3) + (lane & 7);
                int col = kk + ((mi & 1) << 3);
                uint32_t a = bb + (row * RS + col) * 2;
                LDSM_X4(bf[2 * p][0], bf[2 * p][1], bf[2 * p + 1][0], bf[2 * p + 1][1], a);
            }
#pragma unroll
            for (int mt = 0; mt < 4; mt++)
#pragma unroll
                for (int nt = 0; nt < 4; nt++)
                    MMA_F16(acc[mt][nt], af[mt][0], af[mt][1], af[mt][2], af[mt][3],
                            bf[nt][0], bf[nt][1]);
        }
    }

    // Epilogue: bias + activation, write g_gates fp16
#pragma unroll
    for (int mt = 0; mt < 4; mt++) {
#pragma unroll
        for (int nt = 0; nt < 4; nt++) {
            int r   = m0 + warp_m * 64 + mt * 16 + (lane >> 2);
            int cgl = n0 + warp_n * 32 + nt * 8 + ((lane & 3) << 1);
            bool isz = (cgl < 256);
            float b0 = __ldg(bias + cgl);
            float b1 = __ldg(bias + cgl + 1);
            float v0 = acc[mt][nt][0] + b0;
            float v1 = acc[mt][nt][1] + b1;
            float v2 = acc[mt][nt][2] + b0;
            float v3 = acc[mt][nt][3] + b1;
            if (isz) {
                v0 = tanh_fast(v0); v1 = tanh_fast(v1);
                v2 = tanh_fast(v2); v3 = tanh_fast(v3);
            } else {
                v0 = sigm(v0); v1 = sigm(v1);
                v2 = sigm(v2); v3 = sigm(v3);
            }
            *(__half2*)&g_gates[(long)r * N_ + cgl]       = __floats2half2_rn(v0, v1);
            *(__half2*)&g_gates[(long)(r + 8) * N_ + cgl] = __floats2half2_rn(v2, v3);
        }
    }
}

// ---------------------------------------------------------------------------
// Scan pass 1 (R14 config): per (chain-pair, chunk): A = prod(f), B = c(chunk)
// 1024 x 128 thr; 2 h per thread (half2). CHLEN=64. Coalesced float2 stores.
// ---------------------------------------------------------------------------
__global__ __launch_bounds__(128)
void scan_p1()
{
    const int b = blockIdx.x >> 5, q = blockIdx.x & 31, h2 = threadIdx.x;
    const __half2* gp = (const __half2*)(g_gates + (long)(b * S_ + q * CHLEN) * N_) + h2;

    float ax = 1.0f, ay = 1.0f, cx = 0.0f, cy = 0.0f;
    for (int t0 = 0; t0 < CHLEN; t0 += 8) {
        __half2 z2[8], f2[8];
#pragma unroll
        for (int j = 0; j < 8; j++) {
            const __half2* p = gp + (long)(t0 + j) * (N_ / 2);
            z2[j] = __ldg(p);
            f2[j] = __ldg(p + 128);
        }
#pragma unroll
        for (int j = 0; j < 8; j++) {
            float2 z = __half22float2(z2[j]);
            float2 f = __half22float2(f2[j]);
            cx = fmaf(f.x, cx - z.x, z.x);
            cy = fmaf(f.y, cy - z.y, z.y);
            ax *= f.x; ay *= f.y;
        }
    }
    const int chain = b * H_ + 2 * h2;
    *(float2*)&g_Ac[q * CHAINS + chain] = make_float2(ax, ay);
    *(float2*)&g_Bc[q * CHAINS + chain] = make_float2(cx, cy);
}

// ---------------------------------------------------------------------------
// Scan pass 2: warp-parallel Kogge-Stone over the 32 chunk transforms.
// One warp per chain; lane q holds chunk q's (A, B). Composition
// (A2,B2)∘(A1,B1) = (A1*A2, A2*B1 + B2); 5 shfl_up steps; exclusive c0 =
// inclusive B shifted up one lane. 2048 blocks x 128 thr = 8192 warps.
// ---------------------------------------------------------------------------
__global__ __launch_bounds__(128)
void scan_p2()
{
    const int chain = (blockIdx.x * 128 + threadIdx.x) >> 5;
    const int q = threadIdx.x & 31;
    float A  = __ldg(&g_Ac[q * CHAINS + chain]);
    float Bv = __ldg(&g_Bc[q * CHAINS + chain]);
#pragma unroll
    for (int d = 1; d < 32; d <<= 1) {
        float Ap = __shfl_up_sync(0xffffffff, A, d);
        float Bp = __shfl_up_sync(0xffffffff, Bv, d);
        if (q >= d) {
            Bv = fmaf(A, Bp, Bv);   // B = A_later*B_earlier + B_later
            A  = A * Ap;
        }
    }
    float c0 = __shfl_up_sync(0xffffffff, Bv, 1);
    if (q == 0) c0 = 0.0f;
    g_c0[q * CHAINS + chain] = c0;
}

// ---------------------------------------------------------------------------
// Scan pass 3 (R14 config): within-chunk scan with correct initial c.
// 1024 x 128 thr; half2 gates, float2 stores. CHLEN=64.
// ---------------------------------------------------------------------------
__global__ __launch_bounds__(128)
void scan_p3(const int* __restrict__ mask, float* __restrict__ out)
{
    const int b = blockIdx.x >> 5, q = blockIdx.x & 31, h2 = threadIdx.x;
    const int chain = b * H_ + 2 * h2;
    const __half2* gp = (const __half2*)(g_gates + (long)(b * S_ + q * CHLEN) * N_) + h2;

    int idx = mask[b] - 1;
    if (idx < 0) idx = 0;
    if (idx > S_ - 1) idx = S_ - 1;

    float* outT    = out + (long)(b * S_ + q * CHLEN) * H_ + 2 * h2;
    float* outHid  = out + (long)B_ * S_ * H_;
    float* outCell = outHid + B_ * H_;

    float2 c = *(const float2*)&g_c0[q * CHAINS + chain];
    for (int t0 = 0; t0 < CHLEN; t0 += 8) {
        __half2 z2[8], f2[8], o2[8];
#pragma unroll
        for (int j = 0; j < 8; j++) {
            const __half2* p = gp + (long)(t0 + j) * (N_ / 2);
            z2[j] = __ldg(p);
            f2[j] = __ldg(p + 128);
            o2[j] = __ldg(p + 256);
        }
#pragma unroll
        for (int j = 0; j < 8; j++) {
            float2 z = __half22float2(z2[j]);
            float2 f = __half22float2(f2[j]);
            float2 o = __half22float2(o2[j]);
            c.x = fmaf(f.x, c.x - z.x, z.x);
            c.y = fmaf(f.y, c.y - z.y, z.y);
            float2 hv = make_float2(o.x * c.x, o.y * c.y);
            *(float2*)(outT + (long)(t0 + j) * H_) = hv;
            if (q * CHLEN + t0 + j == idx) {
                *(float2*)&outHid[chain]  = hv;
                *(float2*)&outCell[chain] = c;
            }
        }
    }
}

extern "C" void kernel_launch(void* const* d_in, const int* in_sizes, int n_in,
                              void* d_out, int out_size)
{
    const float* x    = (const float*)d_in[0];
    const int*   mask = (const int*)d_in[1];
    const float* W    = (const float*)d_in[2];
    const float* bias = (const float*)d_in[3];
    float* out = (float*)d_out;

    cudaFuncSetAttribute(gates_gemm, cudaFuncAttributeMaxDynamicSharedMemorySize, SMEM_BYTES);

    prep_fused<<<XBLK + WBLK, 256>>>(x, W);
    gates_gemm<<<dim3(6, 512), 256, SMEM_BYTES>>>(bias);
    scan_p1<<<B_ * CHUNKS, 128>>>();
    scan_p2<<<CHAINS / 4, 128>>>();
    scan_p3<<<B_ * CHUNKS, 128>>>(mask, out);
}